// round 3
// baseline (speedup 1.0000x reference)
#include <cuda_runtime.h>

#define BB 128
#define TT 512
#define CC 128

__device__ float g_partial[BB];

typedef unsigned long long u64;

__device__ __forceinline__ u64 fma_f32x2(u64 a, u64 b, u64 c) {
    u64 d;
    asm("fma.rn.f32x2 %0, %1, %2, %3;" : "=l"(d) : "l"(a), "l"(b), "l"(c));
    return d;
}
__device__ __forceinline__ u64 add_f32x2(u64 a, u64 b) {
    u64 d;
    asm("add.rn.f32x2 %0, %1, %2;" : "=l"(d) : "l"(a), "l"(b));
    return d;
}
__device__ __forceinline__ u64 pack2(float lo, float hi) {
    u64 d;
    asm("mov.b64 %0, {%1, %2};" : "=l"(d) : "f"(lo), "f"(hi));
    return d;
}
__device__ __forceinline__ float unpack_sum(u64 v) {
    float lo, hi;
    asm("mov.b64 {%0, %1}, %2;" : "=f"(lo), "=f"(hi) : "l"(v));
    return lo + hi;
}

__device__ __forceinline__ float block_reduce_sum_128(float v, float* sh4) {
    #pragma unroll
    for (int o = 16; o > 0; o >>= 1)
        v += __shfl_xor_sync(0xffffffffu, v, o);
    int w = threadIdx.x >> 5;
    if ((threadIdx.x & 31) == 0) sh4[w] = v;
    __syncthreads();
    float r = (sh4[0] + sh4[1]) + (sh4[2] + sh4[3]);
    __syncthreads();
    return r;
}

__global__ __launch_bounds__(128, 1)
void crf_forward_kernel(const float* __restrict__ feats,
                        const int*   __restrict__ mask,
                        const int*   __restrict__ tags,
                        const float* __restrict__ trans)
{
    const int b = blockIdx.x;
    const int j = threadIdx.x;          // owns class column j

    __shared__ __align__(16) float p_s[2][CC];
    __shared__ float sh4[4];

    // ---- sequence length (contiguous prefix mask) ----
    const int* mrow = mask + b * TT;
    int cnt = 0;
    #pragma unroll
    for (int t = 0; t < 4; t++) cnt += mrow[j + t * 128];
    const int L = (int)block_reduce_sum_128((float)cnt, sh4);

    // ---- E column in packed-pair registers: E2[ii] = (exp(T[2ii][j]), exp(T[2ii+1][j])) ----
    u64 E2[64];
    #pragma unroll
    for (int ii = 0; ii < 64; ii++) {
        float lo = __expf(trans[(2 * ii + 0) * CC + j]);   // exp(-1e5) -> 0
        float hi = __expf(trans[(2 * ii + 1) * CC + j]);
        E2[ii] = pack2(lo, hi);
    }

    // ---- init: p = one-hot(START), m = 0 ----
    p_s[0][j] = (j == CC - 2) ? 1.0f : 0.0f;
    __syncthreads();

    const float* fb = feats + (size_t)b * TT * CC + j;
    float m   = 0.0f;
    float ef0 = __expf(fb[0]);                        // L >= 1 always
    float ef1 = (L > 1) ? __expf(fb[CC]) : 1.0f;
    int cur = 0;

    // ---- forward scan: one barrier per step ----
    for (int t = 0; t < L; t++) {
        // scale factor: previous p[0] (broadcast LDS, latency hidden by matvec)
        float c  = (t == 0) ? 1.0f : p_s[cur][0];
        float rc = __fdividef(1.0f, c);               // MUFU.RCP, off hot chain start

        float ef2 = (t + 2 < L) ? __expf(fb[(size_t)(t + 2) * CC]) : 1.0f;

        // matvec: s_j = sum_i p[i] * E[i][j], packed fp32x2
        const ulonglong2* pv = (const ulonglong2*)p_s[cur];
        u64 acc0 = 0, acc1 = 0, acc2 = 0, acc3 = 0;
        #pragma unroll
        for (int ii = 0; ii < 16; ii++) {
            ulonglong2 q0 = pv[2 * ii + 0];
            ulonglong2 q1 = pv[2 * ii + 1];
            acc0 = fma_f32x2(q0.x, E2[4 * ii + 0], acc0);
            acc1 = fma_f32x2(q0.y, E2[4 * ii + 1], acc1);
            acc2 = fma_f32x2(q1.x, E2[4 * ii + 2], acc2);
            acc3 = fma_f32x2(q1.y, E2[4 * ii + 3], acc3);
        }
        float s = unpack_sum(add_f32x2(add_f32x2(acc0, acc1),
                                       add_f32x2(acc2, acc3)));

        p_s[cur ^ 1][j] = (s * ef0) * rc;
        m += __logf(c);                                // off critical path

        ef0 = ef1; ef1 = ef2;
        cur ^= 1;
        __syncthreads();
    }

    // ---- logZ = m + log( sum_j p[j] * exp(trans[j][STOP]) ) ----
    float contrib = p_s[cur][j] * __expf(trans[j * CC + (CC - 1)]);
    float tot = block_reduce_sum_128(contrib, sh4);
    float logZ = m + __logf(tot);

    // ---- gold path score ----
    const int* tg = tags + b * TT;
    const float* fbase = feats + (size_t)b * TT * CC;
    float sc = 0.0f;
    for (int t = j; t < L; t += 128)
        sc += fbase[(size_t)t * CC + tg[t]];
    for (int k = j; k <= L; k += 128) {
        int prev = (k == 0) ? (CC - 2) : tg[k - 1];
        int curt = (k == L) ? (CC - 1) : tg[k];
        sc += trans[prev * CC + curt];
    }
    float tots = block_reduce_sum_128(sc, sh4);

    if (j == 0) g_partial[b] = logZ - tots;
}

__global__ void crf_finalize_kernel(float* __restrict__ out)
{
    __shared__ float s[BB];
    int tid = threadIdx.x;
    s[tid] = g_partial[tid];
    __syncthreads();
    #pragma unroll
    for (int off = 64; off > 0; off >>= 1) {
        if (tid < off) s[tid] += s[tid + off];
        __syncthreads();
    }
    if (tid == 0) out[0] = s[0] / (float)BB;
}

extern "C" void kernel_launch(void* const* d_in, const int* in_sizes, int n_in,
                              void* d_out, int out_size)
{
    const float* feats = (const float*)d_in[0];
    const int*   mask  = (const int*)  d_in[1];
    const int*   tags  = (const int*)  d_in[2];
    const float* trans = (const float*)d_in[3];
    float* out = (float*)d_out;

    crf_forward_kernel<<<BB, 128>>>(feats, mask, tags, trans);
    crf_finalize_kernel<<<1, BB>>>(out);
}

// round 5
// speedup vs baseline: 1.1569x; 1.1569x over previous
#include <cuda_runtime.h>
#include <cuda_fp16.h>

#define BB 128
#define TT 512
#define CC 128

#define EBIAS 1.25f   // E' = exp(trans - EBIAS), centers fp16 range
#define GROW  4.6f    // expected per-step log growth log(128*E[e^{f+tr-EBIAS}])
#define BETA  0.75f   // renorm damping (poles |z|=0.866)
#define GAMMA 0.01f   // startup normalizer state ~ e^{-GROW}

__device__ float g_partial[BB];

__device__ __forceinline__ float block_reduce_sum_128(float v, float* sh4) {
    #pragma unroll
    for (int o = 16; o > 0; o >>= 1)
        v += __shfl_xor_sync(0xffffffffu, v, o);
    int w = threadIdx.x >> 5;
    if ((threadIdx.x & 31) == 0) sh4[w] = v;
    __syncthreads();
    float r = (sh4[0] + sh4[1]) + (sh4[2] + sh4[3]);
    __syncthreads();
    return r;
}

__global__ __launch_bounds__(128, 1)
void crf_forward_kernel(const float* __restrict__ feats,
                        const int*   __restrict__ mask,
                        const int*   __restrict__ tags,
                        const float* __restrict__ trans)
{
    const int b = blockIdx.x;
    const int j = threadIdx.x;           // owns class column j

    __shared__ __align__(16) __half p_s[2][CC];
    __shared__ __align__(16) float shmax[2][4];
    __shared__ float sh4[4];

    // ---- sequence length (contiguous prefix mask) ----
    const int* mrow = mask + b * TT;
    int cnt = 0;
    #pragma unroll
    for (int t = 0; t < 4; t++) cnt += mrow[j + t * 128];
    const int L = (int)block_reduce_sum_128((float)cnt, sh4);

    // ---- E column, two complementarily-rounded fp16 copies ----
    __half2 E2a[64], E2b[64];
    #pragma unroll
    for (int ii = 0; ii < 64; ii++) {
        float lo = __expf(trans[(2 * ii + 0) * CC + j] - EBIAS); // exp(-1e5)->0
        float hi = __expf(trans[(2 * ii + 1) * CC + j] - EBIAS);
        __half hlo = __float2half_rn(lo), hhi = __float2half_rn(hi);
        E2a[ii] = __halves2half2(hlo, hhi);
        __half blo = __float2half_rn(2.0f * lo - __half2float(hlo));
        __half bhi = __float2half_rn(2.0f * hi - __half2float(hhi));
        E2b[ii] = __halves2half2(blo, bhi);
    }

    // ---- init ----
    p_s[0][j] = __float2half_rn((j == CC - 2) ? 1.0f : 0.0f);
    if (j < 4) { shmax[0][j] = GAMMA; shmax[1][j] = GAMMA; }
    __syncthreads();

    const float* fb = feats + (size_t)b * TT * CC + j;
    float m   = 0.0f;
    float ef0 = __expf(fb[0]);                       // L >= 1 always
    float ef1 = (L > 1) ? __expf(fb[CC]) : 1.0f;
    float vprev = GAMMA;
    int cur = 0;

    // one step of the forward scan, using E-copy Ecol
    auto step = [&](const __half2 (&Ecol)[64], int t) {
        // lagged (2-step-old) block max -> damped normalizer; hidden under matvec
        float4 mq = *(const float4*)shmax[(t ^ 1) & 1];
        float M2 = fmaxf(fmaxf(mq.x, mq.y), fmaxf(mq.z, mq.w));
        float lm    = __logf(M2);
        float inv_c = __expf(-GROW - BETA * lm);

        float ef2 = (t + 2 < L) ? __expf(fb[(size_t)(t + 2) * CC]) : 1.0f;

        // matvec in fp16x2: 16 chains of depth 4
        const uint4* pv = (const uint4*)p_s[cur];
        __half2 acc[16];
        #pragma unroll
        for (int k = 0; k < 16; k++) acc[k] = __floats2half2_rn(0.f, 0.f);
        #pragma unroll
        for (int ii = 0; ii < 16; ii++) {
            uint4 q = pv[ii];
            __half2 p0 = *reinterpret_cast<__half2*>(&q.x);
            __half2 p1 = *reinterpret_cast<__half2*>(&q.y);
            __half2 p2 = *reinterpret_cast<__half2*>(&q.z);
            __half2 p3 = *reinterpret_cast<__half2*>(&q.w);
            acc[(4 * ii + 0) & 15] = __hfma2(p0, Ecol[4 * ii + 0], acc[(4 * ii + 0) & 15]);
            acc[(4 * ii + 1) & 15] = __hfma2(p1, Ecol[4 * ii + 1], acc[(4 * ii + 1) & 15]);
            acc[(4 * ii + 2) & 15] = __hfma2(p2, Ecol[4 * ii + 2], acc[(4 * ii + 2) & 15]);
            acc[(4 * ii + 3) & 15] = __hfma2(p3, Ecol[4 * ii + 3], acc[(4 * ii + 3) & 15]);
        }

        // warp max of 2-step-old stored p (latency hidden under matvec)
        float wm = vprev;
        #pragma unroll
        for (int o = 16; o > 0; o >>= 1)
            wm = fmaxf(wm, __shfl_xor_sync(0xffffffffu, wm, o));
        if ((j & 31) == 0) shmax[t & 1][j >> 5] = wm;

        // one fp16 tree level (depth 5 total), then fp32 finish
        float2 f[8];
        #pragma unroll
        for (int r = 0; r < 8; r++)
            f[r] = __half22float2(__hadd2(acc[2 * r], acc[2 * r + 1]));
        float2 g0 = make_float2(f[0].x + f[1].x, f[0].y + f[1].y);
        float2 g1 = make_float2(f[2].x + f[3].x, f[2].y + f[3].y);
        float2 g2 = make_float2(f[4].x + f[5].x, f[4].y + f[5].y);
        float2 g3 = make_float2(f[6].x + f[7].x, f[6].y + f[7].y);
        float2 h0 = make_float2(g0.x + g1.x, g0.y + g1.y);
        float2 h1 = make_float2(g2.x + g3.x, g2.y + g3.y);
        float s = (h0.x + h1.x) + (h0.y + h1.y);

        float pj = (s * ef0) * inv_c;
        p_s[cur ^ 1][j] = __float2half_rn(pj);
        vprev = pj;
        m += (EBIAS + GROW) + BETA * lm;

        ef0 = ef1; ef1 = ef2;
        cur ^= 1;
        __syncthreads();
    };

    // ---- forward scan, alternating E copies (cancels systematic fp16 bias) ----
    int t = 0;
    while (t < L) {
        step(E2a, t); t++;
        if (t < L) { step(E2b, t); t++; }
    }

    // ---- logZ = m + log( sum_j p[j] * exp(trans[j][STOP]) ) ----
    float contrib = __half2float(p_s[cur][j]) * __expf(trans[j * CC + (CC - 1)]);
    float tot = block_reduce_sum_128(contrib, sh4);
    float logZ = m + __logf(tot);

    // ---- gold path score (fp32 exact) ----
    const int* tg = tags + b * TT;
    const float* fbase = feats + (size_t)b * TT * CC;
    float sc = 0.0f;
    for (int tt = j; tt < L; tt += 128)
        sc += fbase[(size_t)tt * CC + tg[tt]];
    for (int k = j; k <= L; k += 128) {
        int prev = (k == 0) ? (CC - 2) : tg[k - 1];
        int curt = (k == L) ? (CC - 1) : tg[k];
        sc += trans[prev * CC + curt];
    }
    float tots = block_reduce_sum_128(sc, sh4);

    if (j == 0) g_partial[b] = logZ - tots;
}

__global__ void crf_finalize_kernel(float* __restrict__ out)
{
    __shared__ float s[BB];
    int tid = threadIdx.x;
    s[tid] = g_partial[tid];
    __syncthreads();
    #pragma unroll
    for (int off = 64; off > 0; off >>= 1) {
        if (tid < off) s[tid] += s[tid + off];
        __syncthreads();
    }
    if (tid == 0) out[0] = s[0] / (float)BB;
}

extern "C" void kernel_launch(void* const* d_in, const int* in_sizes, int n_in,
                              void* d_out, int out_size)
{
    const float* feats = (const float*)d_in[0];
    const int*   mask  = (const int*)  d_in[1];
    const int*   tags  = (const int*)  d_in[2];
    const float* trans = (const float*)d_in[3];
    float* out = (float*)d_out;

    crf_forward_kernel<<<BB, 128>>>(feats, mask, tags, trans);
    crf_finalize_kernel<<<1, BB>>>(out);
}